// round 5
// baseline (speedup 1.0000x reference)
#include <cuda_runtime.h>
#include <cuda_bf16.h>
#include <math.h>

// ---------------------------------------------------------------------------
// Problem constants
//   B=32, T=512, M = B*T = 16384 rows for all per-timestep matrices.
//   Layers: (Fin, U): (512,1024) (1024,128) (128,23) (151,256) (256,128) (128,8)
// ---------------------------------------------------------------------------

#define GRU_T 512
#define GRU_B 32
#define GRU_M 16384  // B*T

// ---------------------------------------------------------------------------
// Static device scratch (allocation-free rule: __device__ globals)
// ---------------------------------------------------------------------------
__device__ __align__(256) float g_xp [16384ull * 3072];  // xp for current layer (max 3U=3072)
__device__ __align__(256) float g_seq1[16384ull * 1024]; // layer1 output sequence
__device__ __align__(256) float g_cat [16384ull * 151];  // [z1 (128) | ye (23)] concat buffer
__device__ __align__(256) float g_seq4[16384ull * 256];
__device__ __align__(256) float g_seq5[16384ull * 128];
__device__ __align__(256) float g_h   [1024 * 32];       // hidden state, TRANSPOSED [U][32]
__device__ __align__(256) float g_P   [6 * 32 * 3072];   // partial rp buffer [NK][32][3U] (max L1)
__device__ unsigned int g_bar_count;
__device__ unsigned int g_bar_gen;

// ---------------------------------------------------------------------------
// Software grid barrier (all blocks co-resident: grid == #SMs, 1 block/SM fits)
// gen is monotonic across barriers AND across graph replays; count returns to 0.
// ---------------------------------------------------------------------------
__device__ __forceinline__ void grid_sync()
{
    __syncthreads();
    if (threadIdx.x == 0) {
        volatile unsigned int* vgen = &g_bar_gen;
        unsigned int gen = *vgen;
        __threadfence();
        unsigned int ticket = atomicAdd(&g_bar_count, 1u);
        if (ticket == gridDim.x - 1u) {
            atomicExch(&g_bar_count, 0u);
            __threadfence();
            *vgen = gen + 1u;
        } else {
            while (*vgen == gen) { }
            __threadfence();
        }
    }
    __syncthreads();
}

// ---------------------------------------------------------------------------
// GEMM:  C[M=16384, N] = A[M, K](lda) @ W[K, N] + bias[N]
// Tile 128x64, BK=16, 256 threads, 8x4 register microtile.
// ---------------------------------------------------------------------------
__global__ __launch_bounds__(256) void gemm_bias_kernel(
    const float* __restrict__ A, int lda,
    const float* __restrict__ W,
    const float* __restrict__ bias,
    float* __restrict__ C,
    int N, int K, int vecA)
{
    __shared__ float As[128][20];  // [m][k], padded stride 20 (80B, 16B-aligned rows)
    __shared__ float Bs[16][64];   // [k][n]

    const int tid = threadIdx.x;
    const int m0  = blockIdx.y * 128;
    const int n0  = blockIdx.x * 64;
    const int nx  = tid & 15;   // n group: 4 cols
    const int my  = tid >> 4;   // m group: 8 rows (0..15)

    float acc[8][4];
#pragma unroll
    for (int i = 0; i < 8; i++)
#pragma unroll
        for (int j = 0; j < 4; j++) acc[i][j] = 0.f;

    const int vecB = ((N & 3) == 0) ? 1 : 0;

    for (int k0 = 0; k0 < K; k0 += 16) {
        __syncthreads();
        // ---- load A tile: 128 rows x 16 k  (512 float4-equivalents, 2/thread)
        if (vecA) {
#pragma unroll
            for (int e = 0; e < 2; e++) {
                int idx = tid * 2 + e;          // 0..511
                int row = idx >> 2;
                int kq4 = (idx & 3) * 4;
                float4 v = *(const float4*)&A[(size_t)(m0 + row) * lda + k0 + kq4];
                *(float4*)&As[row][kq4] = v;
            }
        } else {
#pragma unroll
            for (int e = 0; e < 2; e++) {
                int idx = tid * 2 + e;
                int row = idx >> 2;
                int kq4 = (idx & 3) * 4;
                const float* ap = &A[(size_t)(m0 + row) * lda + k0 + kq4];
#pragma unroll
                for (int c = 0; c < 4; c++)
                    As[row][kq4 + c] = (k0 + kq4 + c < K) ? ap[c] : 0.f;
            }
        }
        // ---- load B tile: 16 k x 64 n  (1 float4 / thread)
        {
            int r   = tid >> 4;          // 0..15
            int nq4 = (tid & 15) * 4;    // 0..60
            int kg  = k0 + r;
            if (vecB && kg < K && (n0 + nq4 + 3) < N) {
                float4 v = *(const float4*)&W[(size_t)kg * N + n0 + nq4];
                *(float4*)&Bs[r][nq4] = v;
            } else {
#pragma unroll
                for (int c = 0; c < 4; c++) {
                    int ng = n0 + nq4 + c;
                    Bs[r][nq4 + c] = (kg < K && ng < N) ? W[(size_t)kg * N + ng] : 0.f;
                }
            }
        }
        __syncthreads();
        // ---- compute
#pragma unroll
        for (int kk = 0; kk < 16; kk++) {
            float bv[4];
            *(float4*)bv = *(const float4*)&Bs[kk][nx * 4];
            float av[8];
#pragma unroll
            for (int i = 0; i < 8; i++) av[i] = As[my * 8 + i][kk];
#pragma unroll
            for (int i = 0; i < 8; i++)
#pragma unroll
                for (int j = 0; j < 4; j++)
                    acc[i][j] = fmaf(av[i], bv[j], acc[i][j]);
        }
    }
    // ---- store with bias
#pragma unroll
    for (int i = 0; i < 8; i++) {
        int m = m0 + my * 8 + i;
#pragma unroll
        for (int j = 0; j < 4; j++) {
            int n = n0 + nx * 4 + j;
            if (n < N) C[(size_t)m * N + n] = acc[i][j] + bias[n];
        }
    }
}

// ---------------------------------------------------------------------------
// GRU recurrence (persistent, cooperative).
//   h stored transposed: h[u][b] (u major, 32 b contiguous).
//   Phase 1: P[kc][b][j] = sum_{k in chunk kc} h[k][b] * R[k][j]   (tiled GEMM)
//   Phase 2: gates + hidden update + sequence output write.
// Keras reset_after GRU, gate order z|r|h:
//   z = sig(xz + rz); r = sig(xr + rr); hh = act(xh + r*rh); h = z*h + (1-z)*hh
// ---------------------------------------------------------------------------
__global__ __launch_bounds__(256) void gru_rec_kernel(
    const float* __restrict__ xp,   // [M][3U] (row m = b*T + t)
    const float* __restrict__ R,    // [U][3U]
    const float* __restrict__ br,   // [3U] recurrent bias
    float* __restrict__ h,          // [U][32] transposed hidden
    float* __restrict__ P,          // [NK][32][3U]
    float* __restrict__ out1, int os1, int of1,
    float* out2, int os2, int of2,
    int U, int NK, int kchunk, int NT, int actRelu, int vec4)
{
    const int threeU = 3 * U;
    const int tid = threadIdx.x;
    const int tx = tid & 31;    // n group (4 cols)
    const int ty = tid >> 5;    // b group (4 rows), 0..7
    const int nthreads = gridDim.x * blockDim.x;
    const int gtid = blockIdx.x * blockDim.x + tid;

    __shared__ float sH[16][32];
    __shared__ float sR[16][128];

    // zero-init hidden state
    for (int i = gtid; i < 32 * U; i += nthreads) h[i] = 0.f;
    grid_sync();

    const int ntiles = NT * NK;

    for (int t = 0; t < GRU_T; ++t) {
        // ------------- phase 1: partial H@R -------------
        for (int tile = blockIdx.x; tile < ntiles; tile += gridDim.x) {
            int kc = tile % NK;
            int nt = tile / NK;
            int n0 = nt << 7;
            int k0 = kc * kchunk;
            int k1 = min(k0 + kchunk, U);

            float acc[4][4];
#pragma unroll
            for (int i = 0; i < 4; i++)
#pragma unroll
                for (int j = 0; j < 4; j++) acc[i][j] = 0.f;

            for (int ks = k0; ks < k1; ks += 16) {
                __syncthreads();
                // sH[kk][b]  <- h[(ks+kk)*32 + b]  (coalesced, linear)
#pragma unroll
                for (int e = 0; e < 2; e++) {
                    int idx = tid * 2 + e;          // 0..511
                    int kk = idx >> 5;
                    int bb = idx & 31;
                    int kg = ks + kk;
                    sH[kk][bb] = (kg < k1) ? h[kg * 32 + bb] : 0.f;
                }
                // sR[kk][n]
                if (vec4) {
#pragma unroll
                    for (int e = 0; e < 2; e++) {
                        int idx = tid * 2 + e;
                        int kk = idx >> 5;
                        int nc = (idx & 31) << 2;
                        int kg = ks + kk;
                        float4 v = make_float4(0.f, 0.f, 0.f, 0.f);
                        if (kg < k1)
                            v = *(const float4*)&R[(size_t)kg * threeU + n0 + nc];
                        *(float4*)&sR[kk][nc] = v;
                    }
                } else {
                    for (int idx = tid; idx < 16 * 128; idx += 256) {
                        int kk = idx >> 7;
                        int nc = idx & 127;
                        int kg = ks + kk;
                        int ng = n0 + nc;
                        sR[kk][nc] = (kg < k1 && ng < threeU)
                                         ? R[(size_t)kg * threeU + ng] : 0.f;
                    }
                }
                __syncthreads();
#pragma unroll
                for (int kk = 0; kk < 16; kk++) {
                    float4 hb = *(const float4*)&sH[kk][ty << 2];
                    float4 rv = *(const float4*)&sR[kk][tx << 2];
                    float hv[4] = {hb.x, hb.y, hb.z, hb.w};
                    float rw[4] = {rv.x, rv.y, rv.z, rv.w};
#pragma unroll
                    for (int i = 0; i < 4; i++)
#pragma unroll
                        for (int j = 0; j < 4; j++)
                            acc[i][j] = fmaf(hv[i], rw[j], acc[i][j]);
                }
            }
            // write partials (coalesced along n)
#pragma unroll
            for (int i = 0; i < 4; i++) {
                int bb = (ty << 2) + i;
                size_t base = ((size_t)(kc * 32 + bb)) * threeU + n0 + (tx << 2);
#pragma unroll
                for (int j = 0; j < 4; j++) {
                    int ng = n0 + (tx << 2) + j;
                    if (ng < threeU) P[base + j] = acc[i][j];
                }
            }
        }
        grid_sync();

        // ------------- phase 2: gates + h update -------------
        int total = 32 * U;
        for (int oid = gtid; oid < total; oid += nthreads) {
            int b = oid / U;
            int u = oid - b * U;
            float az = br[u], ar = br[U + u], ah = br[2 * U + u];
            for (int kc = 0; kc < NK; kc++) {
                const float* pp = P + ((size_t)(kc * 32 + b)) * threeU;
                az += pp[u];
                ar += pp[U + u];
                ah += pp[2 * U + u];
            }
            const float* xrow = xp + ((size_t)(b * GRU_T + t)) * threeU;
            float z = 1.f / (1.f + expf(-(xrow[u] + az)));
            float r = 1.f / (1.f + expf(-(xrow[U + u] + ar)));
            float hh = xrow[2 * U + u] + r * ah;
            if (actRelu) hh = fmaxf(hh, 0.f);
            float hp = h[(size_t)u * 32 + b];
            float hn = z * hp + (1.f - z) * hh;
            h[(size_t)u * 32 + b] = hn;
            size_t rowo = (size_t)(b * GRU_T + t);
            out1[rowo * os1 + of1 + u] = hn;
            if (out2) out2[rowo * os2 + of2 + u] = hn;
        }
        grid_sync();
    }
}

// ---------------------------------------------------------------------------
// Host launchers
// ---------------------------------------------------------------------------
static void launch_gemm(const float* A, int lda, const float* W, const float* bias,
                        float* C, int N, int K)
{
    dim3 grid((N + 63) / 64, GRU_M / 128);
    int vecA = (((lda & 3) == 0) && ((K & 15) == 0)) ? 1 : 0;
    gemm_bias_kernel<<<grid, 256>>>(A, lda, W, bias, C, N, K, vecA);
}

static void launch_rec(const float* xp, const float* R, const float* br,
                       float* h, float* P,
                       float* out1, int os1, int of1,
                       float* out2, int os2, int of2,
                       int U, int actRelu, int nb)
{
    int threeU = 3 * U;
    int NT = (threeU + 127) / 128;
    int maxNK = nb / NT;
    if (maxNK < 1) maxNK = 1;
    int NKbyK = (U + 15) / 16;
    int NK = (maxNK < NKbyK) ? maxNK : NKbyK;
    if (NK < 1) NK = 1;
    int kchunk = (((U + NK - 1) / NK) + 15) & ~15;
    NK = (U + kchunk - 1) / kchunk;
    int vec4 = (threeU % 128 == 0) ? 1 : 0;
    gru_rec_kernel<<<nb, 256>>>(xp, R, br, h, P,
                                out1, os1, of1, out2, os2, of2,
                                U, NK, kchunk, NT, actRelu, vec4);
}

// ---------------------------------------------------------------------------
// kernel_launch
// Inputs: x, then (k,r,b) x 6 layers. Output: [ye (32*512*23) | yd (32*512*8)].
// ---------------------------------------------------------------------------
extern "C" void kernel_launch(void* const* d_in, const int* in_sizes, int n_in,
                              void* d_out, int out_size)
{
    (void)in_sizes; (void)n_in; (void)out_size;
    const float* x = (const float*)d_in[0];
    const float* Kw[6]; const float* Rw[6]; const float* Bw[6];
    for (int i = 0; i < 6; i++) {
        Kw[i] = (const float*)d_in[1 + 3 * i];
        Rw[i] = (const float*)d_in[2 + 3 * i];
        Bw[i] = (const float*)d_in[3 + 3 * i];
    }
    float* out = (float*)d_out;

    float *xp, *seq1, *cat, *seq4, *seq5, *h, *P;
    cudaGetSymbolAddress((void**)&xp,   g_xp);
    cudaGetSymbolAddress((void**)&seq1, g_seq1);
    cudaGetSymbolAddress((void**)&cat,  g_cat);
    cudaGetSymbolAddress((void**)&seq4, g_seq4);
    cudaGetSymbolAddress((void**)&seq5, g_seq5);
    cudaGetSymbolAddress((void**)&h,    g_h);
    cudaGetSymbolAddress((void**)&P,    g_P);

    int nb = 0;
    cudaDeviceGetAttribute(&nb, cudaDevAttrMultiProcessorCount, 0);
    if (nb <= 0) nb = 148;

    // Layer 1: 512 -> 1024, relu
    launch_gemm(x, 512, Kw[0], Bw[0], xp, 3072, 512);
    launch_rec(xp, Rw[0], Bw[0] + 3072, h, P,
               seq1, 1024, 0, nullptr, 0, 0, 1024, 1, nb);

    // Layer 2: 1024 -> 128, relu  (write into concat buffer cols [0,128))
    launch_gemm(seq1, 1024, Kw[1], Bw[1], xp, 384, 1024);
    launch_rec(xp, Rw[1], Bw[1] + 384, h, P,
               cat, 151, 0, nullptr, 0, 0, 128, 1, nb);

    // Layer 3: 128 -> 23, linear  (ye: concat cols [128,151) AND d_out)
    launch_gemm(cat, 151, Kw[2], Bw[2], xp, 69, 128);
    launch_rec(xp, Rw[2], Bw[2] + 69, h, P,
               cat, 151, 128, out, 23, 0, 23, 0, nb);

    // Layer 4: 151 -> 256, relu
    launch_gemm(cat, 151, Kw[3], Bw[3], xp, 768, 151);
    launch_rec(xp, Rw[3], Bw[3] + 768, h, P,
               seq4, 256, 0, nullptr, 0, 0, 256, 1, nb);

    // Layer 5: 256 -> 128, relu
    launch_gemm(seq4, 256, Kw[4], Bw[4], xp, 384, 256);
    launch_rec(xp, Rw[4], Bw[4] + 384, h, P,
               seq5, 128, 0, nullptr, 0, 0, 128, 1, nb);

    // Layer 6: 128 -> 8, linear (yd -> d_out + 16384*23)
    launch_gemm(seq5, 128, Kw[5], Bw[5], xp, 24, 128);
    launch_rec(xp, Rw[5], Bw[5] + 24, h, P,
               out + (size_t)GRU_M * 23, 8, 0, nullptr, 0, 0, 8, 0, nb);
}

// round 6
// speedup vs baseline: 2.9174x; 2.9174x over previous
#include <cuda_runtime.h>
#include <math.h>

// ---------------------------------------------------------------------------
// B=32, T=512, M=B*T=16384
// Layers (Fin, U): (512,1024) (1024,128) (128,23) (151,256) (256,128) (128,8)
// Wavefront: step s, layer l processes t = s - l.
// ---------------------------------------------------------------------------

#define T512   512
#define NSTEPS (512 + 5)

// ---------------- static device scratch ----------------
__device__ __align__(256) float g_xp [16384ull * 3072];  // layer-0 input projections
__device__ __align__(256) float g_seq1[16384ull * 1024]; // L0 out
__device__ __align__(256) float g_cat [16384ull * 151];  // [L1 out (128) | L2 out (23)]
__device__ __align__(256) float g_seq4[16384ull * 256];  // L3 out
__device__ __align__(256) float g_seq5[16384ull * 128];  // L4 out
__device__ __align__(256) float g_h   [51200];           // hidden states, transposed [u][32]
__device__ __align__(256) float g_P   [600000];          // per-layer partial slots
__device__ unsigned int g_bar_count;
__device__ unsigned int g_bar_gen;

__constant__ int c_U[6]    = {1024, 128, 23, 256, 128, 8};
__constant__ int c_TU[6]   = {3072, 384, 69, 768, 384, 24};
__constant__ int c_IS[6]   = {0, 4, 1, 1, 1, 1};     // # input partial slots
__constant__ int c_NS[6]   = {4, 5, 2, 2, 2, 2};     // total partial slots
__constant__ int c_PO[6]   = {0, 393216, 454656, 459072, 508224, 532800};
__constant__ int c_HO[6]   = {0, 32768, 36864, 37600, 45792, 49888};
__constant__ int c_RELU[6] = {1, 1, 0, 1, 1, 0};

struct WParams {
    const float* Kw[6];
    const float* Rw[6];
    const float* Bw[6];
    float* out;
};

// ---------------- grid barrier ----------------
__device__ __forceinline__ void grid_sync()
{
    __threadfence();
    __syncthreads();
    if (threadIdx.x == 0) {
        volatile unsigned int* vgen = &g_bar_gen;
        unsigned int gen = *vgen;
        unsigned int ticket = atomicAdd(&g_bar_count, 1u);
        if (ticket == gridDim.x - 1u) {
            atomicExch(&g_bar_count, 0u);
            __threadfence();
            *vgen = gen + 1u;
        } else {
            while (*vgen == gen) { }
            __threadfence();
        }
    }
    __syncthreads();
}

// ---------------- packed f32x2 helpers ----------------
__device__ __forceinline__ void ffma2(unsigned long long& acc,
                                      unsigned long long a, unsigned long long b)
{
    asm("fma.rn.f32x2 %0, %1, %2, %0;" : "+l"(acc) : "l"(a), "l"(b));
}
__device__ __forceinline__ unsigned long long dup2(float x)
{
    unsigned long long r;
    asm("mov.b64 %0, {%1, %1};" : "=l"(r) : "r"(__float_as_uint(x)));
    return r;
}

// ---------------------------------------------------------------------------
// GEMM for layer-0 input projections:
//   C[16384,3072] = X[16384,512] @ K1[512,3072] + b1_i
// ---------------------------------------------------------------------------
__global__ __launch_bounds__(256) void gemm_bias_kernel(
    const float* __restrict__ A, int lda,
    const float* __restrict__ W,
    const float* __restrict__ bias,
    float* __restrict__ C,
    int N, int K)
{
    __shared__ float As[128][20];
    __shared__ float Bs[16][64];

    const int tid = threadIdx.x;
    const int m0  = blockIdx.y * 128;
    const int n0  = blockIdx.x * 64;
    const int nx  = tid & 15;
    const int my  = tid >> 4;

    float acc[8][4];
#pragma unroll
    for (int i = 0; i < 8; i++)
#pragma unroll
        for (int j = 0; j < 4; j++) acc[i][j] = 0.f;

    for (int k0 = 0; k0 < K; k0 += 16) {
        __syncthreads();
#pragma unroll
        for (int e = 0; e < 2; e++) {
            int idx = tid * 2 + e;
            int row = idx >> 2;
            int kq4 = (idx & 3) * 4;
            float4 v = *(const float4*)&A[(size_t)(m0 + row) * lda + k0 + kq4];
            *(float4*)&As[row][kq4] = v;
        }
        {
            int r   = tid >> 4;
            int nq4 = (tid & 15) * 4;
            float4 v = *(const float4*)&W[(size_t)(k0 + r) * N + n0 + nq4];
            *(float4*)&Bs[r][nq4] = v;
        }
        __syncthreads();
#pragma unroll
        for (int kk = 0; kk < 16; kk++) {
            float bv[4];
            *(float4*)bv = *(const float4*)&Bs[kk][nx * 4];
            float av[8];
#pragma unroll
            for (int i = 0; i < 8; i++) av[i] = As[my * 8 + i][kk];
#pragma unroll
            for (int i = 0; i < 8; i++)
#pragma unroll
                for (int j = 0; j < 4; j++)
                    acc[i][j] = fmaf(av[i], bv[j], acc[i][j]);
        }
    }
#pragma unroll
    for (int i = 0; i < 8; i++) {
        int m = m0 + my * 8 + i;
#pragma unroll
        for (int j = 0; j < 4; j++) {
            int n = n0 + nx * 4 + j;
            C[(size_t)m * N + n] = acc[i][j] + bias[n];
        }
    }
}

// ---------------------------------------------------------------------------
// Persistent wavefront kernel: all 6 GRU layers, 517 steps.
// Phase 1: each block computes one 32x128 partial GEMM tile (input or
//          recurrent projection) into g_P.
// Phase 2: whole grid does gate math + hidden update + output writes.
// ---------------------------------------------------------------------------
__global__ __launch_bounds__(256, 1) void wavefront_kernel(WParams prm)
{
    __shared__ float sH[16][36];   // [k][b], padded
    __shared__ float sR[16][128];  // [k][n]

    const int tid   = threadIdx.x;
    const int bid   = blockIdx.x;
    const int gsize = gridDim.x * blockDim.x;
    const int gtid  = bid * blockDim.x + tid;

    // zero all hidden states
    for (int i = gtid; i < 51200; i += gsize) g_h[i] = 0.f;
    grid_sync();

    // ---- static tile schedule (133 tiles) ----
    int layer = -1, n0 = 0, k0 = 0, k1 = 0, slot = 0, src = 0; // src: 0=input, 1=recurrent
    {
        int b = bid;
        if      (b <  96) { layer = 0; src = 1; int nt = b >> 2, kc = b & 3; n0 = nt * 128; slot = kc; k0 = kc * 256; k1 = k0 + 256; }
        else if (b < 108) { int i = b - 96; layer = 1; src = 0; int nt = i >> 2, kc = i & 3; n0 = nt * 128; slot = kc; k0 = kc * 256; k1 = k0 + 256; }
        else if (b < 111) { layer = 1; src = 1; n0 = (b - 108) * 128; slot = 4; k0 = 0; k1 = 128; }
        else if (b == 111){ layer = 2; src = 0; n0 = 0; slot = 0; k0 = 0; k1 = 128; }
        else if (b == 112){ layer = 2; src = 1; n0 = 0; slot = 1; k0 = 0; k1 = 23;  }
        else if (b < 119) { layer = 3; src = 0; n0 = (b - 113) * 128; slot = 0; k0 = 0; k1 = 151; }
        else if (b < 125) { layer = 3; src = 1; n0 = (b - 119) * 128; slot = 1; k0 = 0; k1 = 256; }
        else if (b < 128) { layer = 4; src = 0; n0 = (b - 125) * 128; slot = 0; k0 = 0; k1 = 256; }
        else if (b < 131) { layer = 4; src = 1; n0 = (b - 128) * 128; slot = 1; k0 = 0; k1 = 128; }
        else if (b == 131){ layer = 5; src = 0; n0 = 0; slot = 0; k0 = 0; k1 = 128; }
        else if (b == 132){ layer = 5; src = 1; n0 = 0; slot = 1; k0 = 0; k1 = 8;   }
    }

    int threeU = 0, instride = 0;
    const float* W = nullptr;
    const float* hbase = nullptr;
    const float* inbuf = nullptr;
    float* Pb = nullptr;
    if (layer >= 0) {
        threeU = c_TU[layer];
        W      = src ? prm.Rw[layer] : prm.Kw[layer];
        hbase  = g_h + c_HO[layer];
        switch (layer) {
            case 1: inbuf = g_seq1; instride = 1024; break;
            case 2: inbuf = g_cat;  instride = 151;  break;
            case 3: inbuf = g_cat;  instride = 151;  break;
            case 4: inbuf = g_seq4; instride = 256;  break;
            case 5: inbuf = g_seq5; instride = 128;  break;
            default: break;
        }
        Pb = g_P + c_PO[layer] + (size_t)slot * 32 * threeU;
    }
    const int tx = tid & 31;
    const int ty = tid >> 5;

    for (int s = 0; s < NSTEPS; ++s) {
        // ===================== phase 1 =====================
        if (layer >= 0) {
            int t = s - layer;
            if ((unsigned)t < 512u) {
                unsigned long long acc[2][4];
#pragma unroll
                for (int i = 0; i < 2; i++) { acc[i][0] = 0; acc[i][1] = 0; acc[i][2] = 0; acc[i][3] = 0; }

                float pH0, pH1;
                float pR[8];

#define LOADSTG(KS) {                                                               \
    int _ks = (KS);                                                                 \
    if (src) {                                                                      \
        int kg0 = _ks + (tid >> 5);                                                 \
        int kg1 = _ks + (tid >> 5) + 8;                                             \
        pH0 = (kg0 < k1) ? __ldcg(hbase + kg0 * 32 + (tid & 31)) : 0.f;             \
        pH1 = (kg1 < k1) ? __ldcg(hbase + kg1 * 32 + (tid & 31)) : 0.f;             \
    } else {                                                                        \
        int kg = _ks + (tid & 15);                                                  \
        int b0 = tid >> 4;                                                          \
        const float* rp0 = inbuf + (size_t)(b0 * 512 + t) * instride;               \
        const float* rp1 = inbuf + (size_t)((b0 + 16) * 512 + t) * instride;        \
        pH0 = (kg < k1) ? __ldcg(rp0 + kg) : 0.f;                                   \
        pH1 = (kg < k1) ? __ldcg(rp1 + kg) : 0.f;                                   \
    }                                                                               \
    _Pragma("unroll")                                                               \
    for (int e = 0; e < 8; e++) {                                                   \
        int idx = tid + 256 * e;                                                    \
        int kg  = _ks + (idx >> 7);                                                 \
        int ng  = n0 + (idx & 127);                                                 \
        pR[e] = (kg < k1 && ng < threeU) ? __ldg(W + (size_t)kg * threeU + ng) : 0.f; \
    } }

                LOADSTG(k0);
                for (int ks = k0; ks < k1; ks += 16) {
                    // commit staged regs to smem
                    if (src) {
                        sH[tid >> 5][tid & 31] = pH0;
                        sH[(tid >> 5) + 8][tid & 31] = pH1;
                    } else {
                        sH[tid & 15][tid >> 4] = pH0;
                        sH[tid & 15][(tid >> 4) + 16] = pH1;
                    }
#pragma unroll
                    for (int e = 0; e < 8; e++) {
                        int idx = tid + 256 * e;
                        sR[idx >> 7][idx & 127] = pR[e];
                    }
                    __syncthreads();
                    if (ks + 16 < k1) LOADSTG(ks + 16);
                    // compute: 32x128 tile, microtile 4(b) x 4(n), f32x2-packed over b
#pragma unroll
                    for (int kk = 0; kk < 16; kk++) {
                        const unsigned long long* hp =
                            (const unsigned long long*)&sH[kk][ty << 2];
                        unsigned long long h0 = hp[0], h1 = hp[1];
                        float4 rv = *(const float4*)&sR[kk][tx << 2];
                        unsigned long long w0 = dup2(rv.x), w1 = dup2(rv.y);
                        unsigned long long w2 = dup2(rv.z), w3 = dup2(rv.w);
                        ffma2(acc[0][0], h0, w0); ffma2(acc[0][1], h0, w1);
                        ffma2(acc[0][2], h0, w2); ffma2(acc[0][3], h0, w3);
                        ffma2(acc[1][0], h1, w0); ffma2(acc[1][1], h1, w1);
                        ffma2(acc[1][2], h1, w2); ffma2(acc[1][3], h1, w3);
                    }
                    __syncthreads();
                }
#undef LOADSTG
                // store partials
#pragma unroll
                for (int i2 = 0; i2 < 2; i2++) {
#pragma unroll
                    for (int hf = 0; hf < 2; hf++) {
                        int b = (ty << 2) + (i2 << 1) + hf;
                        float* dst = Pb + (size_t)b * threeU + n0 + (tx << 2);
#pragma unroll
                        for (int j = 0; j < 4; j++) {
                            unsigned int u32 = hf ? (unsigned int)(acc[i2][j] >> 32)
                                                  : (unsigned int)acc[i2][j];
                            if (n0 + (tx << 2) + j < threeU)
                                dst[j] = __uint_as_float(u32);
                        }
                    }
                }
            }
        }
        grid_sync();

        // ===================== phase 2 =====================
        for (int l = 0; l < 6; l++) {
            int t = s - l;
            if ((unsigned)t >= 512u) continue;
            int U  = c_U[l];
            int tU = c_TU[l];
            const float* Bl = prm.Bw[l];
            for (int oid = gtid; oid < 32 * U; oid += gsize) {
                int b = oid / U;
                int u = oid - b * U;
                size_t row = (size_t)(b * 512 + t);
                float xz, xr, xh;
                if (l == 0) {
                    const float* xrow = g_xp + row * 3072;
                    xz = xrow[u]; xr = xrow[1024 + u]; xh = xrow[2048 + u];
                } else {
                    xz = Bl[u]; xr = Bl[U + u]; xh = Bl[2 * U + u];
                    for (int s2 = 0; s2 < c_IS[l]; s2++) {
                        const float* pp = g_P + c_PO[l] + ((size_t)s2 * 32 + b) * tU;
                        xz += __ldcg(pp + u);
                        xr += __ldcg(pp + U + u);
                        xh += __ldcg(pp + 2 * U + u);
                    }
                }
                const float* Br = Bl + tU;
                float rz = Br[u], rr = Br[U + u], rh = Br[2 * U + u];
                for (int s2 = c_IS[l]; s2 < c_NS[l]; s2++) {
                    const float* pp = g_P + c_PO[l] + ((size_t)s2 * 32 + b) * tU;
                    rz += __ldcg(pp + u);
                    rr += __ldcg(pp + U + u);
                    rh += __ldcg(pp + 2 * U + u);
                }
                float z = 1.f / (1.f + __expf(-(xz + rz)));
                float r = 1.f / (1.f + __expf(-(xr + rr)));
                float hh = xh + r * rh;
                if (c_RELU[l]) hh = fmaxf(hh, 0.f);
                float hp = __ldcg(g_h + c_HO[l] + u * 32 + b);
                float hn = z * hp + (1.f - z) * hh;
                g_h[c_HO[l] + u * 32 + b] = hn;
                switch (l) {
                    case 0: g_seq1[row * 1024 + u] = hn; break;
                    case 1: g_cat[row * 151 + u] = hn; break;
                    case 2: g_cat[row * 151 + 128 + u] = hn;
                            prm.out[row * 23 + u] = hn; break;
                    case 3: g_seq4[row * 256 + u] = hn; break;
                    case 4: g_seq5[row * 128 + u] = hn; break;
                    default: prm.out[16384ull * 23 + row * 8 + u] = hn; break;
                }
            }
        }
        grid_sync();
    }
}

// ---------------------------------------------------------------------------
// kernel_launch: 1 GEMM (layer-0 input projections) + 1 persistent wavefront.
// ---------------------------------------------------------------------------
extern "C" void kernel_launch(void* const* d_in, const int* in_sizes, int n_in,
                              void* d_out, int out_size)
{
    (void)in_sizes; (void)n_in; (void)out_size;
    const float* x = (const float*)d_in[0];

    WParams prm;
    for (int i = 0; i < 6; i++) {
        prm.Kw[i] = (const float*)d_in[1 + 3 * i];
        prm.Rw[i] = (const float*)d_in[2 + 3 * i];
        prm.Bw[i] = (const float*)d_in[3 + 3 * i];
    }
    prm.out = (float*)d_out;

    float* xp;
    cudaGetSymbolAddress((void**)&xp, g_xp);

    // layer-0 input projection GEMM: [16384,512] @ [512,3072] + b
    dim3 grid(3072 / 64, 16384 / 128);
    gemm_bias_kernel<<<grid, 256>>>(x, 512, prm.Kw[0], prm.Bw[0], xp, 3072, 512);

    int nb = 0;
    cudaDeviceGetAttribute(&nb, cudaDevAttrMultiProcessorCount, 0);
    if (nb <= 0 || nb < 133) nb = 148;
    if (nb > 152) nb = 152;

    wavefront_kernel<<<nb, 256>>>(prm);
}

// round 7
// speedup vs baseline: 3.9428x; 1.3515x over previous
#include <cuda_runtime.h>
#include <math.h>

// ---------------------------------------------------------------------------
// B=32, T=512, M=16384.  Layers (Fin,U): (512,1024)(1024,128)(128,23)
// (151,256)(256,128)(128,8).  Wavefront: step s, layer l does t = s - l.
// ---------------------------------------------------------------------------
#define NSTEPS 517

__device__ __align__(256) float g_xp [16384ull * 3072];
__device__ __align__(256) float g_seq1[16384ull * 1024];
__device__ __align__(256) float g_cat [16384ull * 151];
__device__ __align__(256) float g_seq4[16384ull * 256];
__device__ __align__(256) float g_seq5[16384ull * 128];
__device__ __align__(256) float g_h   [50144];     // [b][U] per layer, concat
__device__ __align__(256) float g_P   [600000];    // partial slots
__device__ unsigned int g_bar_count;
__device__ unsigned int g_bar_gen;

__constant__ int c_U[6]  = {1024, 128, 23, 256, 128, 8};
__constant__ int c_TU[6] = {3072, 384, 69, 768, 384, 24};
__constant__ int c_PO[6] = {0, 393216, 454656, 459072, 508224, 532800};
__constant__ int c_HO[6] = {0, 32768, 36864, 37600, 45792, 49888};

struct WParams {
    const float* Kw[6];
    const float* Rw[6];
    const float* Bw[6];
    float* out;
};

// ---------------- lean grid barrier (release/acquire) ----------------
__device__ __forceinline__ void grid_sync()
{
    __syncthreads();
    if (threadIdx.x == 0) {
        unsigned int gen;
        asm volatile("ld.relaxed.gpu.u32 %0, [%1];"
                     : "=r"(gen) : "l"(&g_bar_gen) : "memory");
        unsigned int prev;
        asm volatile("atom.release.gpu.add.u32 %0, [%1], %2;"
                     : "=r"(prev) : "l"(&g_bar_count), "r"(1u) : "memory");
        if (prev == gridDim.x - 1u) {
            unsigned int zero = 0;
            asm volatile("st.relaxed.gpu.u32 [%0], %1;"
                         :: "l"(&g_bar_count), "r"(zero) : "memory");
            asm volatile("st.release.gpu.u32 [%0], %1;"
                         :: "l"(&g_bar_gen), "r"(gen + 1u) : "memory");
        } else {
            unsigned int cur;
            do {
                asm volatile("ld.acquire.gpu.u32 %0, [%1];"
                             : "=r"(cur) : "l"(&g_bar_gen) : "memory");
            } while (cur == gen);
        }
    }
    __syncthreads();
}

// ---------------- packed f32x2 helpers ----------------
__device__ __forceinline__ void ffma2(unsigned long long& acc,
                                      unsigned long long a, unsigned long long b)
{
    asm("fma.rn.f32x2 %0, %1, %2, %0;" : "+l"(acc) : "l"(a), "l"(b));
}
__device__ __forceinline__ unsigned long long dup2(float x)
{
    unsigned long long r;
    asm("mov.b64 %0, {%1, %1};" : "=l"(r) : "r"(__float_as_uint(x)));
    return r;
}
__device__ __forceinline__ float sigf(float x)
{
    return 1.f / (1.f + __expf(-x));
}

// ---------------------------------------------------------------------------
// GEMM for layer-0 input projections: C[16384,3072] = X[16384,512]@K1 + b
// ---------------------------------------------------------------------------
__global__ __launch_bounds__(256) void gemm_bias_kernel(
    const float* __restrict__ A, int lda,
    const float* __restrict__ W,
    const float* __restrict__ bias,
    float* __restrict__ C,
    int N, int K)
{
    __shared__ float As[128][20];
    __shared__ float Bs[16][64];

    const int tid = threadIdx.x;
    const int m0  = blockIdx.y * 128;
    const int n0  = blockIdx.x * 64;
    const int nx  = tid & 15;
    const int my  = tid >> 4;

    float acc[8][4];
#pragma unroll
    for (int i = 0; i < 8; i++)
#pragma unroll
        for (int j = 0; j < 4; j++) acc[i][j] = 0.f;

    for (int k0 = 0; k0 < K; k0 += 16) {
        __syncthreads();
#pragma unroll
        for (int e = 0; e < 2; e++) {
            int idx = tid * 2 + e;
            int row = idx >> 2;
            int kq4 = (idx & 3) * 4;
            float4 v = *(const float4*)&A[(size_t)(m0 + row) * lda + k0 + kq4];
            *(float4*)&As[row][kq4] = v;
        }
        {
            int r   = tid >> 4;
            int nq4 = (tid & 15) * 4;
            float4 v = *(const float4*)&W[(size_t)(k0 + r) * N + n0 + nq4];
            *(float4*)&Bs[r][nq4] = v;
        }
        __syncthreads();
#pragma unroll
        for (int kk = 0; kk < 16; kk++) {
            float bv[4];
            *(float4*)bv = *(const float4*)&Bs[kk][nx * 4];
            float av[8];
#pragma unroll
            for (int i = 0; i < 8; i++) av[i] = As[my * 8 + i][kk];
#pragma unroll
            for (int i = 0; i < 8; i++)
#pragma unroll
                for (int j = 0; j < 4; j++)
                    acc[i][j] = fmaf(av[i], bv[j], acc[i][j]);
        }
    }
#pragma unroll
    for (int i = 0; i < 8; i++) {
        int m = m0 + my * 8 + i;
#pragma unroll
        for (int j = 0; j < 4; j++) {
            int n = n0 + nx * 4 + j;
            C[(size_t)m * N + n] = acc[i][j] + bias[n];
        }
    }
}

// ---------------------------------------------------------------------------
// Phase-2 gate math, one output element, compile-time layer constants.
// ---------------------------------------------------------------------------
template<int L, int U, int TU, int IS, int NS, int PO, int HO, int RELU>
__device__ __forceinline__ void gate_one(int r, int s, const WParams& prm)
{
    int t = s - L;
    if ((unsigned)t >= 512u) return;
    int b = r / U;
    int u = r - b * U;
    size_t row = (size_t)b * 512 + t;

    const float* Bl = prm.Bw[L];
    float xz, xr, xh;
    if (L == 0) {
        const float* xrow = g_xp + row * 3072;
        xz = xrow[u]; xr = xrow[1024 + u]; xh = xrow[2048 + u];
    } else {
        xz = Bl[u]; xr = Bl[U + u]; xh = Bl[2 * U + u];
#pragma unroll
        for (int s2 = 0; s2 < IS; s2++) {
            const float* pp = g_P + PO + ((size_t)s2 * 32 + b) * TU;
            xz += __ldcg(pp + u);
            xr += __ldcg(pp + U + u);
            xh += __ldcg(pp + 2 * U + u);
        }
    }
    const float* Br = Bl + TU;
    float rz = Br[u], rr = Br[U + u], rh = Br[2 * U + u];
#pragma unroll
    for (int s2 = IS; s2 < NS; s2++) {
        const float* pp = g_P + PO + ((size_t)s2 * 32 + b) * TU;
        rz += __ldcg(pp + u);
        rr += __ldcg(pp + U + u);
        rh += __ldcg(pp + 2 * U + u);
    }
    float z  = sigf(xz + rz);
    float rg = sigf(xr + rr);
    float hh = xh + rg * rh;
    if (RELU) hh = fmaxf(hh, 0.f);
    float* hptr = g_h + HO + b * U + u;
    float hp = __ldcg(hptr);
    float hn = z * hp + (1.f - z) * hh;
    *hptr = hn;
    if (L == 0)      g_seq1[row * 1024 + u] = hn;
    else if (L == 1) g_cat[row * 151 + u] = hn;
    else if (L == 2) { g_cat[row * 151 + 128 + u] = hn;
                       prm.out[row * 23 + u] = hn; }
    else if (L == 3) g_seq4[row * 256 + u] = hn;
    else if (L == 4) g_seq5[row * 128 + u] = hn;
    else             prm.out[16384ull * 23 + row * 8 + u] = hn;
}

// ---------------------------------------------------------------------------
// Persistent wavefront kernel.
// Dynamic smem: sW [256][128] weights (resident), sH [256][34] staged slice.
// ---------------------------------------------------------------------------
__global__ __launch_bounds__(256, 1) void wavefront_kernel(WParams prm)
{
    extern __shared__ float smem[];
    float* sW = smem;                 // 32768 floats
    float* sH = smem + 32768;         // 256*34 = 8704 floats

    const int tid   = threadIdx.x;
    const int bid   = blockIdx.x;
    const int gsize = gridDim.x * blockDim.x;
    const int gtid  = bid * blockDim.x + tid;

    // ---- static tile schedule (133 tiles) ----
    int layer = -1, n0 = 0, k0 = 0, k1 = 0, slot = 0, src = 0;
    {
        int b = bid;
        if      (b <  96) { layer = 0; src = 1; int nt = b >> 2, kc = b & 3; n0 = nt * 128; slot = kc; k0 = kc * 256; k1 = k0 + 256; }
        else if (b < 108) { int i = b - 96; layer = 1; src = 0; int nt = i >> 2, kc = i & 3; n0 = nt * 128; slot = kc; k0 = kc * 256; k1 = k0 + 256; }
        else if (b < 111) { layer = 1; src = 1; n0 = (b - 108) * 128; slot = 4; k0 = 0; k1 = 128; }
        else if (b == 111){ layer = 2; src = 0; n0 = 0; slot = 0; k0 = 0; k1 = 128; }
        else if (b == 112){ layer = 2; src = 1; n0 = 0; slot = 1; k0 = 0; k1 = 23;  }
        else if (b < 119) { layer = 3; src = 0; n0 = (b - 113) * 128; slot = 0; k0 = 0; k1 = 151; }
        else if (b < 125) { layer = 3; src = 1; n0 = (b - 119) * 128; slot = 1; k0 = 0; k1 = 256; }
        else if (b < 128) { layer = 4; src = 0; n0 = (b - 125) * 128; slot = 0; k0 = 0; k1 = 256; }
        else if (b < 131) { layer = 4; src = 1; n0 = (b - 128) * 128; slot = 1; k0 = 0; k1 = 128; }
        else if (b == 131){ layer = 5; src = 0; n0 = 0; slot = 0; k0 = 0; k1 = 128; }
        else if (b == 132){ layer = 5; src = 1; n0 = 0; slot = 1; k0 = 0; k1 = 8;   }
    }

    int threeU = 0, instride = 0, Ul = 0, klen = 0;
    const float* hbase = nullptr;
    const float* inbuf = nullptr;
    float* Pb = nullptr;

    if (layer >= 0) {
        threeU = c_TU[layer];
        Ul     = c_U[layer];
        klen   = k1 - k0;
        hbase  = g_h + c_HO[layer];
        switch (layer) {
            case 1: inbuf = g_seq1; instride = 1024; break;
            case 2: inbuf = g_cat;  instride = 151;  break;
            case 3: inbuf = g_cat;  instride = 151;  break;
            case 4: inbuf = g_seq4; instride = 256;  break;
            case 5: inbuf = g_seq5; instride = 128;  break;
            default: break;
        }
        Pb = g_P + c_PO[layer] + (size_t)slot * 32 * threeU;

        // ---- preload weight tile into smem (once) ----
        const float* W = src ? prm.Rw[layer] : prm.Kw[layer];
        for (int idx = tid; idx < klen * 128; idx += 256) {
            int kg = idx >> 7;
            int ng = idx & 127;
            float v = 0.f;
            if (n0 + ng < threeU)
                v = W[(size_t)(k0 + kg) * threeU + n0 + ng];
            sW[kg * 128 + ng] = v;
        }
    }

    // zero hidden states
    for (int i = gtid; i < 50144; i += gsize) g_h[i] = 0.f;
    grid_sync();

    // lane mapping for phase-1 compute: b-group x n-group within warp
    const int lane = tid & 31;
    const int wid  = tid >> 5;
    const int bg4  = (lane >> 2) << 2;                 // 0,4,...,28
    const int ng4  = (wid << 4) + ((lane & 3) << 2);   // 0..124 step 4
    const int nch  = (klen + 31) >> 5;

    for (int s = 0; s < NSTEPS; ++s) {
        // ===================== phase 1 =====================
        if (layer >= 0) {
            int t = s - layer;
            if ((unsigned)t < 512u) {
                // ---- stage h / input slice into sH[k][34] ----
                for (int cc = wid; cc < (nch << 5); cc += 8) {
                    int bb = cc & 31;
                    int kg = ((cc >> 5) << 5) + lane;
                    float v = 0.f;
                    if (kg < klen) {
                        const float* p = src
                            ? (hbase + bb * Ul + k0 + kg)
                            : (inbuf + ((size_t)(bb * 512 + t)) * instride + k0 + kg);
                        v = __ldcg(p);
                    }
                    sH[kg * 34 + bb] = v;
                }
                __syncthreads();

                // ---- compute 32x128 partial tile ----
                unsigned long long acc[2][4];
#pragma unroll
                for (int i = 0; i < 2; i++)
#pragma unroll
                    for (int j = 0; j < 4; j++) acc[i][j] = 0ull;

#pragma unroll 8
                for (int kk = 0; kk < klen; kk++) {
                    const unsigned long long* hp =
                        (const unsigned long long*)(sH + kk * 34 + bg4);
                    unsigned long long h0 = hp[0], h1 = hp[1];
                    float4 rv = *(const float4*)(sW + kk * 128 + ng4);
                    unsigned long long w0 = dup2(rv.x), w1 = dup2(rv.y);
                    unsigned long long w2 = dup2(rv.z), w3 = dup2(rv.w);
                    ffma2(acc[0][0], h0, w0); ffma2(acc[0][1], h0, w1);
                    ffma2(acc[0][2], h0, w2); ffma2(acc[0][3], h0, w3);
                    ffma2(acc[1][0], h1, w0); ffma2(acc[1][1], h1, w1);
                    ffma2(acc[1][2], h1, w2); ffma2(acc[1][3], h1, w3);
                }

                // ---- store partials ----
#pragma unroll
                for (int i2 = 0; i2 < 2; i2++) {
#pragma unroll
                    for (int hf = 0; hf < 2; hf++) {
                        int b = bg4 + (i2 << 1) + hf;
                        float* dst = Pb + (size_t)b * threeU + n0 + ng4;
#pragma unroll
                        for (int j = 0; j < 4; j++) {
                            unsigned int u32 = hf ? (unsigned int)(acc[i2][j] >> 32)
                                                  : (unsigned int)acc[i2][j];
                            if (n0 + ng4 + j < threeU)
                                dst[j] = __uint_as_float(u32);
                        }
                    }
                }
            }
        }
        grid_sync();

        // ===================== phase 2 (flattened) =====================
        for (int oid = gtid; oid < 50144; oid += gsize) {
            if (oid < 32768)
                gate_one<0, 1024, 3072, 0, 4, 0,      0,     1>(oid,         s, prm);
            else if (oid < 36864)
                gate_one<1, 128,  384,  4, 5, 393216, 32768, 1>(oid - 32768, s, prm);
            else if (oid < 37600)
                gate_one<2, 23,   69,   1, 2, 454656, 36864, 0>(oid - 36864, s, prm);
            else if (oid < 45792)
                gate_one<3, 256,  768,  1, 2, 459072, 37600, 1>(oid - 37600, s, prm);
            else if (oid < 49888)
                gate_one<4, 128,  384,  1, 2, 508224, 45792, 1>(oid - 45792, s, prm);
            else
                gate_one<5, 8,    24,   1, 2, 532800, 49888, 0>(oid - 49888, s, prm);
        }
        grid_sync();
    }
}

// ---------------------------------------------------------------------------
// kernel_launch
// ---------------------------------------------------------------------------
extern "C" void kernel_launch(void* const* d_in, const int* in_sizes, int n_in,
                              void* d_out, int out_size)
{
    (void)in_sizes; (void)n_in; (void)out_size;
    const float* x = (const float*)d_in[0];

    WParams prm;
    for (int i = 0; i < 6; i++) {
        prm.Kw[i] = (const float*)d_in[1 + 3 * i];
        prm.Rw[i] = (const float*)d_in[2 + 3 * i];
        prm.Bw[i] = (const float*)d_in[3 + 3 * i];
    }
    prm.out = (float*)d_out;

    float* xp;
    cudaGetSymbolAddress((void**)&xp, g_xp);

    // layer-0 input projection GEMM
    dim3 grid(3072 / 64, 16384 / 128);
    gemm_bias_kernel<<<grid, 256>>>(x, 512, prm.Kw[0], prm.Bw[0], xp, 3072, 512);

    int nb = 0;
    cudaDeviceGetAttribute(&nb, cudaDevAttrMultiProcessorCount, 0);
    if (nb < 133) nb = 148;
    if (nb > 152) nb = 152;

    const int smem_bytes = (32768 + 256 * 34) * 4;  // 165888
    cudaFuncSetAttribute(wavefront_kernel,
                         cudaFuncAttributeMaxDynamicSharedMemorySize, smem_bytes);
    wavefront_kernel<<<nb, 256, smem_bytes>>>(prm);
}